// round 4
// baseline (speedup 1.0000x reference)
#include <cuda_runtime.h>
#include <cuda_fp8.h>
#include <cuda_fp16.h>
#include <math.h>

// Problem shape (fixed for this problem instance)
#define T 1024
#define H 2880
#define NI 2880
#define NEXP 8
#define TOPK 2
#define R1 5760          // 2*I rows of gate_up
#define G 90             // H/32 == I/32 (fp4 groups along K)
#define NA 2048          // total assignments = T*TOPK

// ---------------- scratch (device globals; no allocation allowed) ----------
__device__ float g_xq[T * H];          // mxfp8-qdq'd hidden states
__device__ float g_act[NA * NI];       // swiglu activations (then qdq'd in place)
__device__ float g_out2[NA * H];       // per-assignment expert outputs
__device__ int   g_tok[NA];            // assignment row -> token id
__device__ int   g_pair_row[NA];       // (t*2+k) -> assignment row
__device__ int   g_cnt[NEXP];
__device__ int   g_off[NEXP];

__device__ const float FP4_TBL[16] = {
    0.0f, 0.5f, 1.0f, 1.5f, 2.0f, 3.0f, 4.0f, 6.0f,
    -0.0f, -0.5f, -1.0f, -1.5f, -2.0f, -3.0f, -4.0f, -6.0f};

// ---------------- expert grouping (deterministic) --------------------------
__global__ void build_lists_kernel(const int* __restrict__ eidx) {
    __shared__ int se[NA];
    __shared__ int offs[NEXP];
    int tid = threadIdx.x;
    for (int i = tid; i < NA; i += 256) se[i] = eidx[i];
    __syncthreads();
    if (tid < NEXP) {
        int c = 0;
        for (int i = 0; i < NA; i++) c += (se[i] == tid);
        g_cnt[tid] = c;
    }
    __syncthreads();
    if (tid == 0) {
        int s = 0;
        for (int e = 0; e < NEXP; e++) { offs[e] = s; g_off[e] = s; s += g_cnt[e]; }
    }
    __syncthreads();
    if (tid < NEXP) {
        int pos = offs[tid];
        for (int i = 0; i < NA; i++) {
            if (se[i] == tid) {
                g_tok[pos] = i >> 1;      // token id
                g_pair_row[i] = pos;      // (t,k) -> row
                pos++;
            }
        }
    }
}

// ---------------- MXFP8 quantize-dequantize --------------------------------
// One warp per 32-element block. Exact ceil(log2(maxabs)) via frexp; HW e4m3
// round-to-nearest-even convert matches ml_dtypes.
__device__ __forceinline__ void qdq_block(const float* __restrict__ in,
                                          float* __restrict__ out, int nblk) {
    int w = (blockIdx.x * blockDim.x + threadIdx.x) >> 5;
    int lane = threadIdx.x & 31;
    if (w >= nblk) return;
    size_t idx = (size_t)w * 32 + lane;
    float v = in[idx];
    float a = fabsf(v);
#pragma unroll
    for (int o = 16; o; o >>= 1) a = fmaxf(a, __shfl_xor_sync(0xffffffffu, a, o));
    a = fmaxf(a, 1e-12f);
    int k; float m = frexpf(a, &k);       // a = m * 2^k, m in [0.5, 1)
    int ee = (m == 0.5f) ? (k - 1) : k;   // exact ceil(log2(a))
    ee = max(-127, min(128, ee));
    float inv = ldexpf(1.0f, -ee);
    float scale = ldexpf(1.0f, ee);
    __nv_fp8_storage_t q = __nv_cvt_float_to_fp8(v * inv, __NV_SATFINITE, __NV_E4M3);
    __half_raw hr = __nv_cvt_fp8_to_halfraw(q, __NV_E4M3);
    float deq = __half2float(*(__half*)&hr);
    out[idx] = deq * scale;
}

__global__ void qdq_hidden_kernel(const float* __restrict__ hidden) {
    qdq_block(hidden, g_xq, T * G);
}
__global__ void qdq_act_kernel() {
    qdq_block(g_act, g_act, NA * G);
}

// ---------------- GEMM tiles -----------------------------------------------
#define BM 128
#define BN 64
#define BK 32
// 256 threads, each computes 8x4 of the 128x64 tile.

// GEMM1: act_pre = xq[tok] @ Wgu[e]^T + bias, fused swiglu -> g_act
__global__ __launch_bounds__(256, 2) void gemm1_kernel(
    const int* __restrict__ wblocks, const int* __restrict__ wscales,
    const float* __restrict__ wbias) {
    int e = blockIdx.z;
    int cnt = g_cnt[e];
    int m0 = blockIdx.y * BM;
    if (m0 >= cnt) return;
    int off = g_off[e];
    int nt = blockIdx.x;

    __shared__ float As[BK][BM];
    __shared__ float Bs[BK][BN];
    __shared__ float lut[16];
    int tid = threadIdx.x;
    if (tid < 16) lut[tid] = FP4_TBL[tid];

    // A-load mapping: 2 threads per row, 16 consecutive k each
    int a_m = tid >> 1;
    int a_k = (tid & 1) << 4;
    bool aval = (m0 + a_m) < cnt;
    int tok = aval ? g_tok[off + m0 + a_m] : 0;
    const float* aptr = g_xq + (size_t)tok * H + a_k;

    // B-load mapping: 4 threads per weight row, 4 packed int32 each
    int b_n = tid >> 2;
    int b_sub = (tid & 3) << 2;
    int wrow = e * R1 + nt * BN + b_n;
    const int* bptr = wblocks + (size_t)wrow * (G * 16) + b_sub;
    const int* sptr = wscales + (size_t)wrow * G;

    float acc[8][4];
#pragma unroll
    for (int i = 0; i < 8; i++)
#pragma unroll
        for (int j = 0; j < 4; j++) acc[i][j] = 0.0f;

    int ty = tid >> 4, tx = tid & 15;

    for (int g = 0; g < G; ++g) {
        __syncthreads();
        if (aval) {
            const float4* s4 = (const float4*)(aptr + g * 32);
#pragma unroll
            for (int j = 0; j < 4; j++) {
                float4 v = s4[j];
                As[a_k + 4 * j + 0][a_m] = v.x;
                As[a_k + 4 * j + 1][a_m] = v.y;
                As[a_k + 4 * j + 2][a_m] = v.z;
                As[a_k + 4 * j + 3][a_m] = v.w;
            }
        } else {
#pragma unroll
            for (int j = 0; j < 16; j++) As[a_k + j][a_m] = 0.0f;
        }
        {
            float sc = ldexpf(1.0f, sptr[g] - 127);
            int4 pv = *(const int4*)(bptr + g * 16);
            int vv[4] = {pv.x, pv.y, pv.z, pv.w};
#pragma unroll
            for (int j = 0; j < 4; j++) {
                Bs[2 * (b_sub + j) + 0][b_n] = lut[vv[j] & 15] * sc;
                Bs[2 * (b_sub + j) + 1][b_n] = lut[(vv[j] >> 4) & 15] * sc;
            }
        }
        __syncthreads();
#pragma unroll
        for (int kk = 0; kk < BK; kk++) {
            float4 a0 = *(const float4*)&As[kk][ty * 8];
            float4 a1 = *(const float4*)&As[kk][ty * 8 + 4];
            float4 bv = *(const float4*)&Bs[kk][tx * 4];
            float av[8] = {a0.x, a0.y, a0.z, a0.w, a1.x, a1.y, a1.z, a1.w};
            float bb[4] = {bv.x, bv.y, bv.z, bv.w};
#pragma unroll
            for (int i = 0; i < 8; i++)
#pragma unroll
                for (int j = 0; j < 4; j++)
                    acc[i][j] = fmaf(av[i], bb[j], acc[i][j]);
        }
    }

    // Fused swiglu epilogue. Thread owns 4 consecutive h-columns = 2 act cols.
    int nb = nt * BN + tx * 4;
    float b0 = wbias[e * R1 + nb + 0];
    float b1 = wbias[e * R1 + nb + 1];
    float b2 = wbias[e * R1 + nb + 2];
    float b3 = wbias[e * R1 + nb + 3];
    int jcol = nb >> 1;
#pragma unroll
    for (int i = 0; i < 8; i++) {
        int m = m0 + ty * 8 + i;
        if (m < cnt) {
            float* arow = g_act + (size_t)(off + m) * NI;
            float he = acc[i][0] + b0, ho = acc[i][1] + b1;
            float gate = fminf(he, 7.0f);
            float up = fminf(fmaxf(ho, -7.0f), 7.0f);
            float glu = gate / (1.0f + expf(-1.702f * gate));
            arow[jcol] = (up + 1.0f) * glu;
            he = acc[i][2] + b2; ho = acc[i][3] + b3;
            gate = fminf(he, 7.0f);
            up = fminf(fmaxf(ho, -7.0f), 7.0f);
            glu = gate / (1.0f + expf(-1.702f * gate));
            arow[jcol + 1] = (up + 1.0f) * glu;
        }
    }
}

// GEMM2: out2 = act_q @ Wd[e]^T + bias
__global__ __launch_bounds__(256, 2) void gemm2_kernel(
    const int* __restrict__ wblocks, const int* __restrict__ wscales,
    const float* __restrict__ wbias) {
    int e = blockIdx.z;
    int cnt = g_cnt[e];
    int m0 = blockIdx.y * BM;
    if (m0 >= cnt) return;
    int off = g_off[e];
    int nt = blockIdx.x;

    __shared__ float As[BK][BM];
    __shared__ float Bs[BK][BN];
    __shared__ float lut[16];
    int tid = threadIdx.x;
    if (tid < 16) lut[tid] = FP4_TBL[tid];

    int a_m = tid >> 1;
    int a_k = (tid & 1) << 4;
    bool aval = (m0 + a_m) < cnt;
    const float* aptr = g_act + (size_t)(off + (aval ? (m0 + a_m) : 0)) * NI + a_k;

    int b_n = tid >> 2;
    int b_sub = (tid & 3) << 2;
    int wrow = e * H + nt * BN + b_n;
    const int* bptr = wblocks + (size_t)wrow * (G * 16) + b_sub;
    const int* sptr = wscales + (size_t)wrow * G;

    float acc[8][4];
#pragma unroll
    for (int i = 0; i < 8; i++)
#pragma unroll
        for (int j = 0; j < 4; j++) acc[i][j] = 0.0f;

    int ty = tid >> 4, tx = tid & 15;

    for (int g = 0; g < G; ++g) {
        __syncthreads();
        if (aval) {
            const float4* s4 = (const float4*)(aptr + g * 32);
#pragma unroll
            for (int j = 0; j < 4; j++) {
                float4 v = s4[j];
                As[a_k + 4 * j + 0][a_m] = v.x;
                As[a_k + 4 * j + 1][a_m] = v.y;
                As[a_k + 4 * j + 2][a_m] = v.z;
                As[a_k + 4 * j + 3][a_m] = v.w;
            }
        } else {
#pragma unroll
            for (int j = 0; j < 16; j++) As[a_k + j][a_m] = 0.0f;
        }
        {
            float sc = ldexpf(1.0f, sptr[g] - 127);
            int4 pv = *(const int4*)(bptr + g * 16);
            int vv[4] = {pv.x, pv.y, pv.z, pv.w};
#pragma unroll
            for (int j = 0; j < 4; j++) {
                Bs[2 * (b_sub + j) + 0][b_n] = lut[vv[j] & 15] * sc;
                Bs[2 * (b_sub + j) + 1][b_n] = lut[(vv[j] >> 4) & 15] * sc;
            }
        }
        __syncthreads();
#pragma unroll
        for (int kk = 0; kk < BK; kk++) {
            float4 a0 = *(const float4*)&As[kk][ty * 8];
            float4 a1 = *(const float4*)&As[kk][ty * 8 + 4];
            float4 bv = *(const float4*)&Bs[kk][tx * 4];
            float av[8] = {a0.x, a0.y, a0.z, a0.w, a1.x, a1.y, a1.z, a1.w};
            float bb[4] = {bv.x, bv.y, bv.z, bv.w};
#pragma unroll
            for (int i = 0; i < 8; i++)
#pragma unroll
                for (int j = 0; j < 4; j++)
                    acc[i][j] = fmaf(av[i], bb[j], acc[i][j]);
        }
    }

    int nb = nt * BN + tx * 4;
    float b0 = wbias[e * H + nb + 0];
    float b1 = wbias[e * H + nb + 1];
    float b2 = wbias[e * H + nb + 2];
    float b3 = wbias[e * H + nb + 3];
#pragma unroll
    for (int i = 0; i < 8; i++) {
        int m = m0 + ty * 8 + i;
        if (m < cnt) {
            float4 r;
            r.x = acc[i][0] + b0;
            r.y = acc[i][1] + b1;
            r.z = acc[i][2] + b2;
            r.w = acc[i][3] + b3;
            *(float4*)(g_out2 + (size_t)(off + m) * H + nb) = r;
        }
    }
}

// ---------------- combine (atomic-free, deterministic) ---------------------
__global__ void combine_kernel(const float* __restrict__ rw,
                               float* __restrict__ out) {
    int t = blockIdx.x;
    int r0 = g_pair_row[t * 2 + 0];
    int r1 = g_pair_row[t * 2 + 1];
    float w0 = rw[t * 2 + 0];
    float w1 = rw[t * 2 + 1];
    const float* p0 = g_out2 + (size_t)r0 * H;
    const float* p1 = g_out2 + (size_t)r1 * H;
    float* po = out + (size_t)t * H;
    for (int n = threadIdx.x; n < H; n += blockDim.x)
        po[n] = w0 * p0[n] + w1 * p1[n];
}

// ---------------- launch ----------------------------------------------------
extern "C" void kernel_launch(void* const* d_in, const int* in_sizes, int n_in,
                              void* d_out, int out_size) {
    const float* hidden = (const float*)d_in[0];
    const int*   eidx   = (const int*)d_in[1];
    const float* rw     = (const float*)d_in[2];
    const int*   gub    = (const int*)d_in[3];
    const int*   gus    = (const int*)d_in[4];
    const float* gubias = (const float*)d_in[5];
    const int*   db     = (const int*)d_in[6];
    const int*   ds     = (const int*)d_in[7];
    const float* dbias  = (const float*)d_in[8];
    float* out = (float*)d_out;

    build_lists_kernel<<<1, 256>>>(eidx);

    {   // qdq hidden states: T*G warps, 8 warps/block
        int blocks = (T * G + 7) / 8;
        qdq_hidden_kernel<<<blocks, 256>>>(hidden);
    }

    {   // GEMM1 + swiglu
        dim3 grid(R1 / BN, NA / BM, NEXP);   // (90, 16, 8)
        gemm1_kernel<<<grid, 256>>>(gub, gus, gubias);
    }

    {   // qdq activations in place
        int blocks = (NA * G + 7) / 8;
        qdq_act_kernel<<<blocks, 256>>>();
    }

    {   // GEMM2
        dim3 grid(H / BN, NA / BM, NEXP);    // (45, 16, 8)
        gemm2_kernel<<<grid, 256>>>(db, ds, dbias);
    }

    combine_kernel<<<T, 256>>>(rw, out);
}

// round 7
// speedup vs baseline: 3.6708x; 3.6708x over previous
#include <cuda_runtime.h>
#include <cuda_bf16.h>
#include <cuda_fp8.h>
#include <cuda_fp16.h>
#include <math.h>
#include <stdint.h>

// Problem shape (fixed)
#define T 1024
#define H 2880
#define NI 2880
#define NEXP 8
#define R1 5760          // 2*I rows of gate_up
#define G 90             // K groups of 32
#define NA 2048          // T * topk

// GEMM tile
#define BM 128
#define BN 64
#define BK 32
#define ASTR 40          // padded row stride in bf16 elems (80 bytes)
#define ASTRB 80

// ---------------- scratch ---------------------------------------------------
__device__ __nv_bfloat16 g_xq[T * H];      // qdq'd hidden, bf16 (exact)
__device__ float         g_act[NA * NI];   // swiglu activations fp32
__device__ __nv_bfloat16 g_actb[NA * NI];  // qdq'd activations, bf16 (exact)
__device__ float         g_out2[NA * H];   // per-assignment outputs
__device__ int g_tok[NA], g_pair_row[NA], g_cnt[NEXP], g_off[NEXP];

__device__ const float FP4_TBL[16] = {
    0.0f, 0.5f, 1.0f, 1.5f, 2.0f, 3.0f, 4.0f, 6.0f,
    -0.0f, -0.5f, -1.0f, -1.5f, -2.0f, -3.0f, -4.0f, -6.0f};

// ---------------- expert grouping (deterministic) ---------------------------
__global__ void build_lists_kernel(const int* __restrict__ eidx) {
    __shared__ int se[NA];
    __shared__ int offs[NEXP];
    int tid = threadIdx.x;
    for (int i = tid; i < NA; i += 256) se[i] = eidx[i];
    __syncthreads();
    if (tid < NEXP) {
        int c = 0;
        for (int i = 0; i < NA; i++) c += (se[i] == tid);
        g_cnt[tid] = c;
    }
    __syncthreads();
    if (tid == 0) {
        int s = 0;
        for (int e = 0; e < NEXP; e++) { offs[e] = s; g_off[e] = s; s += g_cnt[e]; }
    }
    __syncthreads();
    if (tid < NEXP) {
        int pos = offs[tid];
        for (int i = 0; i < NA; i++) {
            if (se[i] == tid) {
                g_tok[pos] = i >> 1;
                g_pair_row[i] = pos;
                pos++;
            }
        }
    }
}

// ---------------- MXFP8 qdq -> bf16 -----------------------------------------
__device__ __forceinline__ void qdq_block_bf16(const float* __restrict__ in,
                                               __nv_bfloat16* __restrict__ out,
                                               int nblk) {
    int w = (blockIdx.x * blockDim.x + threadIdx.x) >> 5;
    int lane = threadIdx.x & 31;
    if (w >= nblk) return;
    size_t idx = (size_t)w * 32 + lane;
    float v = in[idx];
    float a = fabsf(v);
#pragma unroll
    for (int o = 16; o; o >>= 1) a = fmaxf(a, __shfl_xor_sync(0xffffffffu, a, o));
    a = fmaxf(a, 1e-12f);
    int k; float m = frexpf(a, &k);
    int ee = (m == 0.5f) ? (k - 1) : k;     // exact ceil(log2(a))
    ee = max(-127, min(128, ee));
    float inv = ldexpf(1.0f, -ee);
    float scale = ldexpf(1.0f, ee);
    __nv_fp8_storage_t q = __nv_cvt_float_to_fp8(v * inv, __NV_SATFINITE, __NV_E4M3);
    __half_raw hr = __nv_cvt_fp8_to_halfraw(q, __NV_E4M3);
    float deq = __half2float(*(__half*)&hr);
    out[idx] = __float2bfloat16(deq * scale);   // exact: 3-bit mantissa * 2^e
}

__global__ void qdq_hidden_kernel(const float* __restrict__ hidden) {
    qdq_block_bf16(hidden, g_xq, T * G);
}
__global__ void qdq_act_kernel() {
    qdq_block_bf16(g_act, g_actb, NA * G);
}

// ---------------- mma helpers ------------------------------------------------
__device__ __forceinline__ void ldsm_x4(uint32_t* r, uint32_t addr) {
    asm volatile("ldmatrix.sync.aligned.m8n8.x4.shared.b16 {%0,%1,%2,%3}, [%4];\n"
                 : "=r"(r[0]), "=r"(r[1]), "=r"(r[2]), "=r"(r[3]) : "r"(addr));
}
__device__ __forceinline__ void mma16816(float* d, const uint32_t* a,
                                         uint32_t b0, uint32_t b1) {
    asm volatile(
        "mma.sync.aligned.m16n8k16.row.col.f32.bf16.bf16.f32 "
        "{%0,%1,%2,%3}, {%4,%5,%6,%7}, {%8,%9}, {%0,%1,%2,%3};\n"
        : "+f"(d[0]), "+f"(d[1]), "+f"(d[2]), "+f"(d[3])
        : "r"(a[0]), "r"(a[1]), "r"(a[2]), "r"(a[3]), "r"(b0), "r"(b1));
}

// ---------------- tensor-core GEMM (both stages) -----------------------------
// C[BM=128, BN=64] per block; 8 warps of 32x32; K loop over 90 groups of 32.
// A (bf16, K-major) copied to SMEM; B (fp4) dequantized to bf16 in SMEM.
template <bool IS_G1>
__global__ __launch_bounds__(256) void gemm_mma_kernel(
    const int* __restrict__ wblocks, const int* __restrict__ wscales,
    const float* __restrict__ wbias, int NR) {
    int e = blockIdx.z;
    int cnt = g_cnt[e];
    int m0 = blockIdx.y * BM;
    if (m0 >= cnt) return;
    int off = g_off[e];
    int nt = blockIdx.x;

    __shared__ __nv_bfloat16 As[BM * ASTR];
    __shared__ __nv_bfloat16 Bs[BN * ASTR];
    __shared__ float lut[16];
    int tid = threadIdx.x;
    if (tid < 16) lut[tid] = FP4_TBL[tid];

    // --- A global mapping: 2 threads per row, 16 bf16 (32B) each ---
    int a_m = tid >> 1;
    int a_half = tid & 1;
    bool aval = (m0 + a_m) < cnt;
    const __nv_bfloat16* aptr;
    if (IS_G1) {
        int tok = aval ? g_tok[off + m0 + a_m] : 0;
        aptr = g_xq + (size_t)tok * H + a_half * 16;
    } else {
        aptr = g_actb + (size_t)(off + (aval ? (m0 + a_m) : 0)) * NI + a_half * 16;
    }
    // --- B global mapping: 4 threads per weight row, 4 int32 (8 fp4-pairs) ---
    int b_n = tid >> 2;
    int b_i = tid & 3;
    int wrow = e * NR + nt * BN + b_n;
    const int* bptr = wblocks + (size_t)wrow * (G * 16) + b_i * 4;
    const int* sptr = wscales + (size_t)wrow * G;

    uint32_t as_u = (uint32_t)__cvta_generic_to_shared(As);
    uint32_t bs_u = (uint32_t)__cvta_generic_to_shared(Bs);

    // per-warp ldmatrix base addresses
    int wid = tid >> 5, lane = tid & 31;
    int wm = (wid & 3) * 32;
    int wn = (wid >> 2) * 32;
    uint32_t aA = as_u + (uint32_t)(wm + (lane & 15)) * ASTRB + (lane >> 4) * 16;
    uint32_t aB = bs_u + (uint32_t)(wn + (lane & 15)) * ASTRB + (lane >> 4) * 16;

    float acc[2][4][4];
#pragma unroll
    for (int i = 0; i < 2; i++)
#pragma unroll
        for (int j = 0; j < 4; j++)
#pragma unroll
            for (int c = 0; c < 4; c++) acc[i][j][c] = 0.0f;

    // register prefetch of group 0
    uint4 a_pre0 = make_uint4(0, 0, 0, 0), a_pre1 = make_uint4(0, 0, 0, 0);
    if (aval) {
        a_pre0 = *(const uint4*)(aptr);
        a_pre1 = *(const uint4*)(aptr + 8);
    }
    int4 b_pre = *(const int4*)(bptr);
    int s_pre = sptr[0];

    for (int g = 0; g < G; ++g) {
        __syncthreads();   // prior compute done; (g==0: lut visible)
        // store prefetched A
        {
            __nv_bfloat16* d = As + a_m * ASTR + a_half * 16;
            *(uint4*)d = a_pre0;
            *(uint4*)(d + 8) = a_pre1;
        }
        // dequant + store prefetched B
        {
            float sc = ldexpf(1.0f, s_pre - 127);
            int vv[4] = {b_pre.x, b_pre.y, b_pre.z, b_pre.w};
            uint32_t pk[4];
#pragma unroll
            for (int j = 0; j < 4; j++) {
                float lo = lut[vv[j] & 15] * sc;
                float hi = lut[(vv[j] >> 4) & 15] * sc;
                __nv_bfloat162 p = __floats2bfloat162_rn(lo, hi);
                pk[j] = *(uint32_t*)&p;
            }
            uint4 u = make_uint4(pk[0], pk[1], pk[2], pk[3]);
            *(uint4*)(Bs + b_n * ASTR + b_i * 8) = u;
        }
        __syncthreads();
        // prefetch next group while computing current
        if (g + 1 < G) {
            const __nv_bfloat16* ap = aptr + (size_t)(g + 1) * 32;
            if (aval) {
                a_pre0 = *(const uint4*)(ap);
                a_pre1 = *(const uint4*)(ap + 8);
            }
            b_pre = *(const int4*)(bptr + (size_t)(g + 1) * 16);
            s_pre = sptr[g + 1];
        }
#pragma unroll
        for (int s = 0; s < 2; s++) {
            uint32_t A0[4], A1[4], B0[4], B1[4];
            ldsm_x4(A0, aA + s * 32);
            ldsm_x4(A1, aA + 16 * ASTRB + s * 32);
            ldsm_x4(B0, aB + s * 32);
            ldsm_x4(B1, aB + 16 * ASTRB + s * 32);
            mma16816(acc[0][0], A0, B0[0], B0[2]);
            mma16816(acc[0][1], A0, B0[1], B0[3]);
            mma16816(acc[0][2], A0, B1[0], B1[2]);
            mma16816(acc[0][3], A0, B1[1], B1[3]);
            mma16816(acc[1][0], A1, B0[0], B0[2]);
            mma16816(acc[1][1], A1, B0[1], B0[3]);
            mma16816(acc[1][2], A1, B1[0], B1[2]);
            mma16816(acc[1][3], A1, B1[1], B1[3]);
        }
    }

    // ---------------- epilogue ----------------
    int lm = lane >> 2;          // 0..7
    int lc = (lane & 3) * 2;     // even column within n8
#pragma unroll
    for (int ms = 0; ms < 2; ms++) {
#pragma unroll
        for (int nf = 0; nf < 4; nf++) {
            int col = nt * BN + wn + nf * 8 + lc;
            int rbase = m0 + wm + ms * 16 + lm;
            float c0 = acc[ms][nf][0], c1 = acc[ms][nf][1];
            float c2 = acc[ms][nf][2], c3 = acc[ms][nf][3];
            if (IS_G1) {
                float be = wbias[e * R1 + col];
                float bo = wbias[e * R1 + col + 1];
                int j = col >> 1;
                if (rbase < cnt) {
                    float gate = fminf(c0 + be, 7.0f);
                    float up = fminf(fmaxf(c1 + bo, -7.0f), 7.0f);
                    float glu = gate / (1.0f + expf(-1.702f * gate));
                    g_act[(size_t)(off + rbase) * NI + j] = (up + 1.0f) * glu;
                }
                if (rbase + 8 < cnt) {
                    float gate = fminf(c2 + be, 7.0f);
                    float up = fminf(fmaxf(c3 + bo, -7.0f), 7.0f);
                    float glu = gate / (1.0f + expf(-1.702f * gate));
                    g_act[(size_t)(off + rbase + 8) * NI + j] = (up + 1.0f) * glu;
                }
            } else {
                float b0 = wbias[e * H + col];
                float b1 = wbias[e * H + col + 1];
                if (rbase < cnt) {
                    float2 r = make_float2(c0 + b0, c1 + b1);
                    *(float2*)(g_out2 + (size_t)(off + rbase) * H + col) = r;
                }
                if (rbase + 8 < cnt) {
                    float2 r = make_float2(c2 + b0, c3 + b1);
                    *(float2*)(g_out2 + (size_t)(off + rbase + 8) * H + col) = r;
                }
            }
        }
    }
}

// ---------------- combine (deterministic) -----------------------------------
__global__ void combine_kernel(const float* __restrict__ rw,
                               float* __restrict__ out) {
    int t = blockIdx.x;
    int r0 = g_pair_row[t * 2 + 0];
    int r1 = g_pair_row[t * 2 + 1];
    float w0 = rw[t * 2 + 0];
    float w1 = rw[t * 2 + 1];
    const float* p0 = g_out2 + (size_t)r0 * H;
    const float* p1 = g_out2 + (size_t)r1 * H;
    float* po = out + (size_t)t * H;
    for (int n = threadIdx.x; n < H; n += blockDim.x)
        po[n] = w0 * p0[n] + w1 * p1[n];
}

// ---------------- launch ------------------------------------------------------
extern "C" void kernel_launch(void* const* d_in, const int* in_sizes, int n_in,
                              void* d_out, int out_size) {
    const float* hidden = (const float*)d_in[0];
    const int*   eidx   = (const int*)d_in[1];
    const float* rw     = (const float*)d_in[2];
    const int*   gub    = (const int*)d_in[3];
    const int*   gus    = (const int*)d_in[4];
    const float* gubias = (const float*)d_in[5];
    const int*   db     = (const int*)d_in[6];
    const int*   ds     = (const int*)d_in[7];
    const float* dbias  = (const float*)d_in[8];
    float* out = (float*)d_out;

    build_lists_kernel<<<1, 256>>>(eidx);

    {   // qdq hidden -> bf16
        int blocks = (T * G + 7) / 8;
        qdq_hidden_kernel<<<blocks, 256>>>(hidden);
    }
    {   // GEMM1 + swiglu (tensor cores)
        dim3 grid(R1 / BN, NA / BM, NEXP);   // (90, 16, 8)
        gemm_mma_kernel<true><<<grid, 256>>>(gub, gus, gubias, R1);
    }
    {   // qdq activations -> bf16
        int blocks = (NA * G + 7) / 8;
        qdq_act_kernel<<<blocks, 256>>>();
    }
    {   // GEMM2 (tensor cores)
        dim3 grid(H / BN, NA / BM, NEXP);    // (45, 16, 8)
        gemm_mma_kernel<false><<<grid, 256>>>(db, ds, dbias, H);
    }
    combine_kernel<<<T, 256>>>(rw, out);
}